// round 14
// baseline (speedup 1.0000x reference)
#include <cuda_runtime.h>
#include <cstdint>

#define NPTS 16384
#define MCTR 2048
#define FPS_CTAS 8
#define FPS_THREADS 256
#define SLICE (NPTS / FPS_CTAS)
#define PPT (SLICE / FPS_THREADS)

// ---------------- device scratch ----------------
__device__ int    g_bq[4 * MCTR * 64];
__device__ float  g_bufA[50331648];
__device__ float  g_bufB[67108864];
__device__ float2 g_part[4096 * 128];
__device__ float  g_a[128];
__device__ float  g_bb[128];
// precomputed W tf32 split planes, [layer][k][o] (coalesced along o), k<=96, o<=128
__device__ float  g_wH[6][96][128];
__device__ float  g_wL[6][96][128];

__constant__ int c_cin[6]  = {67, 64, 64, 67, 64, 96};
__constant__ int c_cout[6] = {64, 64, 128, 64, 96, 128};

__device__ __forceinline__ float fadd(float a, float b) { return __fadd_rn(a, b); }
__device__ __forceinline__ float fmul(float a, float b) { return __fmul_rn(a, b); }
__device__ __forceinline__ float fsub(float a, float b) { return __fsub_rn(a, b); }

// ---- mbarrier helpers (cluster scope) ----
__device__ __forceinline__ void mbar_init(uint32_t addr, uint32_t count) {
    asm volatile("mbarrier.init.shared.b64 [%0], %1;" :: "r"(addr), "r"(count) : "memory");
}
__device__ __forceinline__ void mbar_wait_cluster(uint32_t addr, uint32_t parity) {
    asm volatile(
        "{\n\t.reg .pred P;\n\t"
        "WAITL_%=:\n\t"
        "mbarrier.try_wait.parity.acquire.cluster.shared::cta.b64 P, [%0], %1, 0x989680;\n\t"
        "@P bra.uni DONEL_%=;\n\t"
        "bra.uni WAITL_%=;\n\t"
        "DONEL_%=:\n\t}"
        :: "r"(addr), "r"(parity) : "memory");
}
__device__ __forceinline__ void mbar_arrive_remote(uint32_t laddr, uint32_t rank) {
    asm volatile(
        "{\n\t.reg .b32 ra;\n\t"
        "mapa.shared::cluster.u32 ra, %0, %1;\n\t"
        "mbarrier.arrive.shared::cluster.b64 _, [ra];\n\t}"
        :: "r"(laddr), "r"(rank) : "memory");
}
__device__ __forceinline__ uint32_t mapa_u32(uint32_t laddr, uint32_t rank) {
    uint32_t ra;
    asm volatile("mapa.shared::cluster.u32 %0, %1, %2;" : "=r"(ra) : "r"(laddr), "r"(rank));
    return ra;
}
__device__ __forceinline__ void st_cluster_b32(uint32_t addr, uint32_t v) {
    asm volatile("st.shared::cluster.b32 [%0], %1;" :: "r"(addr), "r"(v) : "memory");
}
__device__ __forceinline__ uint32_t smem_u32(const void* p) {
    uint32_t a;
    asm("{ .reg .u64 t; cvta.to.shared.u64 t, %1; cvt.u32.u64 %0, t; }" : "=r"(a) : "l"(p));
    return a;
}

__device__ __forceinline__ float to_tf32(float x) {
    float r;
    asm("cvt.rna.tf32.f32 %0, %1;" : "=f"(r) : "f"(x));
    return r;
}

#define MMA_TF32(d, a, b0_, b1_) \
    asm volatile("mma.sync.aligned.m16n8k8.row.col.f32.tf32.tf32.f32 " \
        "{%0,%1,%2,%3}, {%4,%5,%6,%7}, {%8,%9}, {%0,%1,%2,%3};" \
        : "+f"((d)[0]), "+f"((d)[1]), "+f"((d)[2]), "+f"((d)[3]) \
        : "r"((a)[0]), "r"((a)[1]), "r"((a)[2]), "r"((a)[3]), "r"(b0_), "r"(b1_))

// ============ FPS (known-good leader protocol, bit-exact) ============
__global__ __launch_bounds__(FPS_THREADS) __cluster_dims__(FPS_CTAS, 1, 1)
void fps_cluster_kernel(const float* __restrict__ xyz, float* __restrict__ out)
{
    __shared__ float sx[SLICE], sy[SLICE], sz[SLICE];
    __shared__ float swv[8];
    __shared__ int   swi[8];
    __shared__ __align__(16) float cand[8][8];
    __shared__ __align__(16) float res[4];
    __shared__ __align__(8) unsigned long long candBar, resBar;

    const int tid = threadIdx.x;
    const int lane = tid & 31, w = tid >> 5;
    const int b = blockIdx.x / FPS_CTAS;
    uint32_t rank;
    asm("mov.u32 %0, %%cluster_ctarank;" : "=r"(rank));
    const float* X = xyz + (size_t)b * 3 * NPTS;
    const int base = rank * SLICE;

    for (int i = tid; i < SLICE; i += FPS_THREADS) {
        sx[i] = X[base + i];
        sy[i] = X[NPTS + base + i];
        sz[i] = X[2 * NPTS + base + i];
    }
    const uint32_t candBase = smem_u32(&cand[0][0]);
    const uint32_t resBase  = smem_u32(&res[0]);
    const uint32_t candBarA = smem_u32(&candBar);
    const uint32_t resBarA  = smem_u32(&resBar);
    if (tid == 0) {
        mbar_init(candBarA, FPS_CTAS);
        mbar_init(resBarA, 1);
    }
    __syncthreads();
    asm volatile("barrier.cluster.arrive.aligned;" ::: "memory");
    asm volatile("barrier.cluster.wait.aligned;" ::: "memory");

    float xr[PPT], yr[PPT], zr[PPT], dist[PPT];
    const int i0 = tid * PPT;
#pragma unroll
    for (int e = 0; e < PPT; e++) {
        xr[e] = sx[i0 + e]; yr[e] = sy[i0 + e]; zr[e] = sz[i0 + e];
        dist[e] = 1e10f;
    }
    float px = X[0], py = X[NPTS], pz = X[2 * NPTS];
    if (rank == 0 && tid == 0) {
        out[b * 3 * MCTR] = px;
        out[b * 3 * MCTR + MCTR] = py;
        out[b * 3 * MCTR + 2 * MCTR] = pz;
    }

    for (int step = 1; step < MCTR; step++) {
        const uint32_t parity = (uint32_t)((step - 1) & 1);
        float bv = -1.f; int bi = 0;
#pragma unroll
        for (int e = 0; e < PPT; e++) {
            float dx = fsub(xr[e], px), dy = fsub(yr[e], py), dz = fsub(zr[e], pz);
            float d  = fadd(fadd(fmul(dx, dx), fmul(dy, dy)), fmul(dz, dz));
            float nd = fminf(dist[e], d);
            dist[e] = nd;
            if (nd > bv) { bv = nd; bi = base + i0 + e; }
        }
#pragma unroll
        for (int off = 16; off > 0; off >>= 1) {
            float ov = __shfl_down_sync(0xffffffffu, bv, off);
            int   oi = __shfl_down_sync(0xffffffffu, bi, off);
            if (ov > bv || (ov == bv && oi < bi)) { bv = ov; bi = oi; }
        }
        if (lane == 0) { swv[w] = bv; swi[w] = bi; }
        __syncthreads();

        if (w == 0) {
            float v = (lane < 8) ? swv[lane] : -2.f;
            int   i = (lane < 8) ? swi[lane] : 0x7fffffff;
#pragma unroll
            for (int off = 4; off > 0; off >>= 1) {
                float ov = __shfl_xor_sync(0xffffffffu, v, off, 8);
                int   oi = __shfl_xor_sync(0xffffffffu, i, off, 8);
                if (ov > v || (ov == v && oi < i)) { v = ov; i = oi; }
            }
            if (lane == 0) {
                int li = i - base;
                float cx = sx[li], cy = sy[li], cz = sz[li];
                uint32_t ra = mapa_u32(candBase + rank * 32u, 0u);
                st_cluster_b32(ra,      __float_as_uint(v));
                st_cluster_b32(ra + 4,  (uint32_t)i);
                st_cluster_b32(ra + 8,  __float_as_uint(cx));
                st_cluster_b32(ra + 12, __float_as_uint(cy));
                st_cluster_b32(ra + 16, __float_as_uint(cz));
                mbar_arrive_remote(candBarA, 0u);
            }
            if (rank == 0) {
                mbar_wait_cluster(candBarA, parity);
                int rl = lane & 7;
                const float* sp = &cand[rl][0];
                float v2 = sp[0];
                int   i2 = __float_as_int(sp[1]);
                float x2 = sp[2], y2 = sp[3], z2 = sp[4];
#pragma unroll
                for (int off = 4; off > 0; off >>= 1) {
                    float ov = __shfl_xor_sync(0xffffffffu, v2, off, 8);
                    int   oi = __shfl_xor_sync(0xffffffffu, i2, off, 8);
                    float ox = __shfl_xor_sync(0xffffffffu, x2, off, 8);
                    float oy = __shfl_xor_sync(0xffffffffu, y2, off, 8);
                    float oz = __shfl_xor_sync(0xffffffffu, z2, off, 8);
                    if (ov > v2 || (ov == v2 && oi < i2)) { v2 = ov; i2 = oi; x2 = ox; y2 = oy; z2 = oz; }
                }
                if (lane < FPS_CTAS) {
                    uint32_t ra = mapa_u32(resBase, (uint32_t)lane);
                    st_cluster_b32(ra,     __float_as_uint(x2));
                    st_cluster_b32(ra + 4, __float_as_uint(y2));
                    st_cluster_b32(ra + 8, __float_as_uint(z2));
                    mbar_arrive_remote(resBarA, (uint32_t)lane);
                }
                if (lane == 0) {
                    out[b * 3 * MCTR + step] = x2;
                    out[b * 3 * MCTR + MCTR + step] = y2;
                    out[b * 3 * MCTR + 2 * MCTR + step] = z2;
                }
            }
        }
        mbar_wait_cluster(resBarA, parity);
        px = res[0]; py = res[1]; pz = res[2];
    }
}

// ============ W split precompute: [layer][k][o] coalesced planes ============
__global__ void __launch_bounds__(256) wsplit_kernel(const float* w0, const float* w1, const float* w2,
                                                     const float* w3, const float* w4, const float* w5)
{
    const float* Wp[6] = {w0, w1, w2, w3, w4, w5};
    int l = blockIdx.x;
    int Cin = c_cin[l], Cout = c_cout[l];
    const float* W = Wp[l];
    for (int t = threadIdx.x; t < 96 * 128; t += 256) {
        int k = t >> 7, o = t & 127;
        float x = (o < Cout && k < Cin) ? W[o * Cin + k] : 0.f;
        float hi = to_tf32(x);
        float lo = to_tf32(fsub(x, hi));
        g_wH[l][k][o] = hi;
        g_wL[l][k][o] = lo;
    }
}

// ============ Ball query (unchanged) ============
__global__ void __launch_bounds__(256) ballquery_kernel(const float* __restrict__ xyz,
                                                        const float* __restrict__ out,
                                                        int K, float r2)
{
    int warp = (blockIdx.x * blockDim.x + threadIdx.x) >> 5;
    int lane = threadIdx.x & 31;
    int b = warp >> 11, m = warp & (MCTR - 1);
    const float* nx = out + b * 3 * MCTR;
    float cx = nx[m], cy = nx[MCTR + m], cz = nx[2 * MCTR + m];
    float sqc = fadd(fadd(fmul(cx, cx), fmul(cy, cy)), fmul(cz, cz));
    const float* X = xyz + (size_t)b * 3 * NPTS;

    int cnt = 0, firstIdx = 0;
    bool haveFirst = false;
    int* dst = g_bq + (size_t)warp * K;
    for (int base = 0; base < NPTS; base += 32) {
        int n = base + lane;
        float x = X[n], y = X[NPTS + n], z = X[2 * NPTS + n];
        float sqx = fadd(fadd(fmul(x, x), fmul(y, y)), fmul(z, z));
        float dot = fadd(fadd(fmul(cx, x), fmul(cy, y)), fmul(cz, z));
        float d2 = fsub(fadd(sqc, sqx), fmul(2.0f, dot));
        bool pred = d2 < r2;
        unsigned msk = __ballot_sync(0xffffffffu, pred);
        if (!haveFirst && msk) { firstIdx = base + __ffs(msk) - 1; haveFirst = true; }
        if (pred) {
            int pos = cnt + __popc(msk & ((1u << lane) - 1u));
            if (pos < K) dst[pos] = n;
        }
        cnt += __popc(msk);
        if (cnt >= K) break;
    }
    if (cnt < K) {
        int fill = haveFirst ? firstIdx : 0;
        for (int p = cnt + lane; p < K; p += 32) dst[p] = fill;
    }
}

// ============ 3xTF32 tensor-core GEMM (coalesced W plane staging) ============
template <bool BN, bool GATHER>
__global__ void __launch_bounds__(256) mma_gemm_kernel(const float* __restrict__ X,
                                                       float* __restrict__ Y,
                                                       int lidx,
                                                       int Cin, int Kpad, int Cout,
                                                       int ldc, int logK,
                                                       const float* __restrict__ xyz,
                                                       const float* __restrict__ feat,
                                                       const float* __restrict__ ctr)
{
    extern __shared__ __align__(16) float dsm[];
    float* Xh = dsm;
    float* Xl = Xh + (size_t)Kpad * 132;
    float* Wh = Xl + (size_t)Kpad * 132;
    float* Wl = Wh + (size_t)Kpad * 132;
    __shared__ float  sa[128], sb2[128];
    __shared__ int    sidx[128];
    __shared__ float  sctr[3][128];
    __shared__ float2 sstat[2][128];

    const int tid = threadIdx.x;
    const int colBase = blockIdx.x * 128;

    if (BN && tid < Cin) { sa[tid] = g_a[tid]; sb2[tid] = g_bb[tid]; }
    if (GATHER && tid < 128) {
        int col = colBase + tid;
        sidx[tid] = g_bq[col];
        int mg = col >> logK;
        int bb_ = mg >> 11, m = mg & (MCTR - 1);
#pragma unroll
        for (int d = 0; d < 3; d++)
            sctr[d][tid] = ctr[bb_ * 3 * MCTR + d * MCTR + m];
    }
    __syncthreads();

    // ---- W plane staging: fully coalesced from precomputed [k][o] planes ----
    {
        const float* wh = &g_wH[lidx][0][0];
        const float* wl = &g_wL[lidx][0][0];
        for (int t = tid; t < Kpad * 128; t += 256) {
            int j = t & 127, k = t >> 7;
            Wh[k * 132 + j] = wh[t];
            Wl[k * 132 + j] = wl[t];
        }
    }
    // ---- X staging: split into tf32 hi/lo planes ----
    {
        const float* Xp = nullptr;
        const float* Fp = nullptr;
        if (GATHER) {
            int bb_ = colBase >> (logK + 11);
            Xp = xyz + (size_t)bb_ * 3 * NPTS;
            Fp = feat + (size_t)bb_ * 64 * NPTS;
        }
        for (int t = tid; t < Kpad * 128; t += 256) {
            int j = t & 127, k = t >> 7;
            float v = 0.f;
            if (k < Cin) {
                if (GATHER) {
                    int n = sidx[j];
                    if (k < 3) v = Xp[k * NPTS + n] - sctr[k][j];
                    else       v = Fp[(k - 3) * NPTS + n];
                } else {
                    v = X[(size_t)k * ldc + colBase + j];
                    if (BN) v = fmaxf(0.f, fmaf(sa[k], v, sb2[k]));
                }
            }
            float hi = to_tf32(v);
            float lo = to_tf32(fsub(v, hi));
            Xh[k * 132 + j] = hi;
            Xl[k * 132 + j] = lo;
        }
    }
    __syncthreads();

    const int w = tid >> 5, lane = tid & 31;
    const int g = lane >> 2, tg = lane & 3;
    const int mBase = (w & 3) * 32, nBase = (w >> 2) * 64;

    float acc[2][8][4];
#pragma unroll
    for (int mt = 0; mt < 2; mt++)
#pragma unroll
        for (int nt = 0; nt < 8; nt++)
#pragma unroll
            for (int c = 0; c < 4; c++) acc[mt][nt][c] = 0.f;

    for (int k0 = 0; k0 < Kpad; k0 += 8) {
        uint32_t ah[2][4], al[2][4];
        const int kr0 = (k0 + tg) * 132, kr1 = (k0 + tg + 4) * 132;
#pragma unroll
        for (int mt = 0; mt < 2; mt++) {
            int r = mBase + mt * 16 + g;
            ah[mt][0] = __float_as_uint(Wh[kr0 + r]);
            ah[mt][1] = __float_as_uint(Wh[kr0 + r + 8]);
            ah[mt][2] = __float_as_uint(Wh[kr1 + r]);
            ah[mt][3] = __float_as_uint(Wh[kr1 + r + 8]);
            al[mt][0] = __float_as_uint(Wl[kr0 + r]);
            al[mt][1] = __float_as_uint(Wl[kr0 + r + 8]);
            al[mt][2] = __float_as_uint(Wl[kr1 + r]);
            al[mt][3] = __float_as_uint(Wl[kr1 + r + 8]);
        }
#pragma unroll
        for (int nt = 0; nt < 8; nt++) {
            int c = nBase + nt * 8 + g;
            uint32_t bh0 = __float_as_uint(Xh[kr0 + c]);
            uint32_t bh1 = __float_as_uint(Xh[kr1 + c]);
            uint32_t bl0 = __float_as_uint(Xl[kr0 + c]);
            uint32_t bl1 = __float_as_uint(Xl[kr1 + c]);
#pragma unroll
            for (int mt = 0; mt < 2; mt++) {
                MMA_TF32(acc[mt][nt], ah[mt], bl0, bl1);
                MMA_TF32(acc[mt][nt], al[mt], bh0, bh1);
                MMA_TF32(acc[mt][nt], ah[mt], bh0, bh1);
            }
        }
    }
    __syncthreads();   // planes free; reuse as D staging

    // ---- stats from register fragments (deterministic) ----
    {
        float s[4] = {0.f, 0.f, 0.f, 0.f}, q[4] = {0.f, 0.f, 0.f, 0.f};
#pragma unroll
        for (int mt = 0; mt < 2; mt++)
#pragma unroll
            for (int nt = 0; nt < 8; nt++) {
                float v0 = acc[mt][nt][0], v1 = acc[mt][nt][1];
                float v2 = acc[mt][nt][2], v3 = acc[mt][nt][3];
                s[mt * 2 + 0] += v0 + v1; q[mt * 2 + 0] += v0 * v0 + v1 * v1;
                s[mt * 2 + 1] += v2 + v3; q[mt * 2 + 1] += v2 * v2 + v3 * v3;
            }
#pragma unroll
        for (int off = 1; off <= 2; off <<= 1)
#pragma unroll
            for (int i = 0; i < 4; i++) {
                s[i] += __shfl_xor_sync(0xffffffffu, s[i], off);
                q[i] += __shfl_xor_sync(0xffffffffu, q[i], off);
            }
        if (tg == 0) {
            int nw = w >> 2;
            sstat[nw][mBase + g]      = make_float2(s[0], q[0]);
            sstat[nw][mBase + 8 + g]  = make_float2(s[1], q[1]);
            sstat[nw][mBase + 16 + g] = make_float2(s[2], q[2]);
            sstat[nw][mBase + 24 + g] = make_float2(s[3], q[3]);
        }
    }

    // ---- D -> smem staging [row][132] ----
    {
        float* Ds = dsm;
#pragma unroll
        for (int mt = 0; mt < 2; mt++) {
            int r = mBase + mt * 16 + g;
#pragma unroll
            for (int nt = 0; nt < 8; nt++) {
                int c = nBase + nt * 8 + 2 * tg;
                *(float2*)&Ds[r * 132 + c]       = make_float2(acc[mt][nt][0], acc[mt][nt][1]);
                *(float2*)&Ds[(r + 8) * 132 + c] = make_float2(acc[mt][nt][2], acc[mt][nt][3]);
            }
        }
    }
    __syncthreads();

    if (tid < 128) {
        float2 a0 = sstat[0][tid], b0 = sstat[1][tid];
        g_part[(size_t)blockIdx.x * 128 + tid] = make_float2(a0.x + b0.x, a0.y + b0.y);
    }
    {
        const float* Ds = dsm;
        for (int idx = tid; idx < Cout * 32; idx += 256) {
            int o = idx >> 5, jj = idx & 31;
            float4 v = *(const float4*)&Ds[o * 132 + jj * 4];
            *(float4*)&Y[(size_t)o * ldc + colBase + jj * 4] = v;
        }
    }
}

// ============ deterministic stats reduce -> BN scale/shift (unchanged) ============
__global__ void __launch_bounds__(256) reduce_stats_kernel(const float* __restrict__ gam,
                                                           const float* __restrict__ bet,
                                                           int R, float inv_n)
{
    __shared__ float ss[256], sq[256];
    int c = blockIdx.x, tid = threadIdx.x;
    float s = 0.f, q = 0.f;
    for (int r = tid; r < R; r += 256) {
        float2 v = g_part[(size_t)r * 128 + c];
        s += v.x; q += v.y;
    }
    ss[tid] = s; sq[tid] = q;
    __syncthreads();
    for (int off = 128; off > 0; off >>= 1) {
        if (tid < off) { ss[tid] += ss[tid + off]; sq[tid] += sq[tid + off]; }
        __syncthreads();
    }
    if (tid == 0) {
        float mu = ss[0] * inv_n;
        float var = sq[0] * inv_n - mu * mu;
        if (var < 0.f) var = 0.f;
        float a = gam[c] * rsqrtf(var + 1e-5f);
        g_a[c] = a;
        g_bb[c] = bet[c] - mu * a;
    }
}

// ============ BN + ReLU + max over K -> output features (unchanged) ============
__global__ void __launch_bounds__(1024) maxpool_kernel(const float* __restrict__ Y,
                                                       float* __restrict__ out,
                                                       int K, int chanOff, int ldc)
{
    int gw = (blockIdx.x * 1024 + threadIdx.x) >> 5;
    int lane = threadIdx.x & 31;
    int o = gw & 127;
    int mg = gw >> 7;
    int b = mg >> 11, m = mg & (MCTR - 1);
    float a = g_a[o], bb = g_bb[o];
    const float* src = Y + (size_t)o * ldc + (size_t)mg * K;
    float v = 0.f;
    for (int k = lane; k < K; k += 32)
        v = fmaxf(v, fmaf(a, src[k], bb));
#pragma unroll
    for (int off = 16; off > 0; off >>= 1)
        v = fmaxf(v, __shfl_xor_sync(0xffffffffu, v, off));
    if (lane == 0)
        out[24576 + ((size_t)(b * 256 + chanOff + o)) * MCTR + m] = v;
}

// ==================== host side ====================
extern "C" void kernel_launch(void* const* d_in, const int* in_sizes, int n_in,
                              void* d_out, int out_size)
{
    const float* xyz  = (const float*)d_in[0];
    const float* feat = (const float*)d_in[1];
    float* out = (float*)d_out;

    fps_cluster_kernel<<<4 * FPS_CTAS, FPS_THREADS>>>(xyz, out);

    wsplit_kernel<<<6, 256>>>((const float*)d_in[2],  (const float*)d_in[5],  (const float*)d_in[8],
                              (const float*)d_in[11], (const float*)d_in[14], (const float*)d_in[17]);

    const int MAX_DSM = 96 * 132 * 4 * 4;   // 202752 bytes
    cudaFuncSetAttribute(mma_gemm_kernel<false, true>,
                         cudaFuncAttributeMaxDynamicSharedMemorySize, MAX_DSM);
    cudaFuncSetAttribute(mma_gemm_kernel<true, false>,
                         cudaFuncAttributeMaxDynamicSharedMemorySize, MAX_DSM);

    const int KS[2] = {32, 64};
    const float R2[2] = {(float)(0.2 * 0.2), (float)(0.4 * 0.4)};
    const int CH[2][3] = {{64, 64, 128}, {64, 96, 128}};
    const int KPAD[2][3] = {{72, 64, 64}, {72, 64, 96}};

    for (int s = 0; s < 2; s++) {
        int K = KS[s];
        int logK = (K == 32) ? 5 : 6;
        int cols = 4 * MCTR * K;
        int nBlk = cols / 128;
        float inv_n = 1.0f / (float)cols;

        ballquery_kernel<<<1024, 256>>>(xyz, out, K, R2[s]);

        const float *Gl[3], *Bl[3];
        for (int l = 0; l < 3; l++) {
            Gl[l] = (const float*)d_in[2 + s * 9 + l * 3 + 1];
            Bl[l] = (const float*)d_in[2 + s * 9 + l * 3 + 2];
        }
        float *pA, *pB;
        cudaGetSymbolAddress((void**)&pA, g_bufA);
        cudaGetSymbolAddress((void**)&pB, g_bufB);

        int c0 = CH[s][0], c1 = CH[s][1], c2 = CH[s][2];

        // L0: gather fused -> B(c0)
        mma_gemm_kernel<false, true><<<nBlk, 256, KPAD[s][0] * 132 * 16>>>(
            nullptr, pB, s * 3 + 0, 67, KPAD[s][0], c0, cols, logK, xyz, feat, out);
        reduce_stats_kernel<<<c0, 256>>>(Gl[0], Bl[0], nBlk, inv_n);

        // L1: B (bn+relu fused) -> A(c1)
        mma_gemm_kernel<true, false><<<nBlk, 256, KPAD[s][1] * 132 * 16>>>(
            pB, pA, s * 3 + 1, c0, KPAD[s][1], c1, cols, logK, xyz, feat, out);
        reduce_stats_kernel<<<c1, 256>>>(Gl[1], Bl[1], nBlk, inv_n);

        // L2: A (bn+relu fused) -> B(128)
        mma_gemm_kernel<true, false><<<nBlk, 256, KPAD[s][2] * 132 * 16>>>(
            pA, pB, s * 3 + 2, c1, KPAD[s][2], c2, cols, logK, xyz, feat, out);
        reduce_stats_kernel<<<c2, 256>>>(Gl[2], Bl[2], nBlk, inv_n);

        maxpool_kernel<<<(4 * MCTR * 128) / 32, 1024>>>(pB, out, K, s * 128, cols);
    }
}

// round 15
// speedup vs baseline: 1.2619x; 1.2619x over previous
#include <cuda_runtime.h>
#include <cstdint>

#define NPTS 16384
#define MCTR 2048
#define FPS_CTAS 8
#define FPS_THREADS 256
#define SLICE (NPTS / FPS_CTAS)
#define PPT (SLICE / FPS_THREADS)

// ---------------- device scratch ----------------
__device__ int    g_bq[4 * MCTR * 64];
__device__ float  g_bufA[50331648];
__device__ float  g_bufB[67108864];
__device__ float2 g_part[4096 * 128];
__device__ float  g_a[128];
__device__ float  g_bb[128];
// pre-transposed W, [layer][k][o] fp32 (coalesced along o)
__device__ float  g_wT[6][96][128];

__constant__ int c_cin[6]  = {67, 64, 64, 67, 64, 96};
__constant__ int c_cout[6] = {64, 64, 128, 64, 96, 128};

__device__ __forceinline__ float fadd(float a, float b) { return __fadd_rn(a, b); }
__device__ __forceinline__ float fmul(float a, float b) { return __fmul_rn(a, b); }
__device__ __forceinline__ float fsub(float a, float b) { return __fsub_rn(a, b); }

// ---- mbarrier helpers (cluster scope) ----
__device__ __forceinline__ void mbar_init(uint32_t addr, uint32_t count) {
    asm volatile("mbarrier.init.shared.b64 [%0], %1;" :: "r"(addr), "r"(count) : "memory");
}
__device__ __forceinline__ void mbar_wait_cluster(uint32_t addr, uint32_t parity) {
    asm volatile(
        "{\n\t.reg .pred P;\n\t"
        "WAITL_%=:\n\t"
        "mbarrier.try_wait.parity.acquire.cluster.shared::cta.b64 P, [%0], %1, 0x989680;\n\t"
        "@P bra.uni DONEL_%=;\n\t"
        "bra.uni WAITL_%=;\n\t"
        "DONEL_%=:\n\t}"
        :: "r"(addr), "r"(parity) : "memory");
}
__device__ __forceinline__ void mbar_arrive_remote(uint32_t laddr, uint32_t rank) {
    asm volatile(
        "{\n\t.reg .b32 ra;\n\t"
        "mapa.shared::cluster.u32 ra, %0, %1;\n\t"
        "mbarrier.arrive.shared::cluster.b64 _, [ra];\n\t}"
        :: "r"(laddr), "r"(rank) : "memory");
}
__device__ __forceinline__ uint32_t mapa_u32(uint32_t laddr, uint32_t rank) {
    uint32_t ra;
    asm volatile("mapa.shared::cluster.u32 %0, %1, %2;" : "=r"(ra) : "r"(laddr), "r"(rank));
    return ra;
}
__device__ __forceinline__ void st_cluster_b32(uint32_t addr, uint32_t v) {
    asm volatile("st.shared::cluster.b32 [%0], %1;" :: "r"(addr), "r"(v) : "memory");
}
__device__ __forceinline__ uint32_t smem_u32(const void* p) {
    uint32_t a;
    asm("{ .reg .u64 t; cvta.to.shared.u64 t, %1; cvt.u32.u64 %0, t; }" : "=r"(a) : "l"(p));
    return a;
}

__device__ __forceinline__ float to_tf32(float x) {
    float r;
    asm("cvt.rna.tf32.f32 %0, %1;" : "=f"(r) : "f"(x));
    return r;
}
// split fp32 -> (hi, lo) tf32 pair as uint32 regs
__device__ __forceinline__ void split_tf32(float v, uint32_t& hi, uint32_t& lo) {
    float h = to_tf32(v);
    float l = to_tf32(fsub(v, h));
    hi = __float_as_uint(h);
    lo = __float_as_uint(l);
}

#define MMA_TF32(d, a, b0_, b1_) \
    asm volatile("mma.sync.aligned.m16n8k8.row.col.f32.tf32.tf32.f32 " \
        "{%0,%1,%2,%3}, {%4,%5,%6,%7}, {%8,%9}, {%0,%1,%2,%3};" \
        : "+f"((d)[0]), "+f"((d)[1]), "+f"((d)[2]), "+f"((d)[3]) \
        : "r"((a)[0]), "r"((a)[1]), "r"((a)[2]), "r"((a)[3]), "r"(b0_), "r"(b1_))

// ============ FPS (known-good leader protocol, bit-exact) ============
__global__ __launch_bounds__(FPS_THREADS) __cluster_dims__(FPS_CTAS, 1, 1)
void fps_cluster_kernel(const float* __restrict__ xyz, float* __restrict__ out)
{
    __shared__ float sx[SLICE], sy[SLICE], sz[SLICE];
    __shared__ float swv[8];
    __shared__ int   swi[8];
    __shared__ __align__(16) float cand[8][8];
    __shared__ __align__(16) float res[4];
    __shared__ __align__(8) unsigned long long candBar, resBar;

    const int tid = threadIdx.x;
    const int lane = tid & 31, w = tid >> 5;
    const int b = blockIdx.x / FPS_CTAS;
    uint32_t rank;
    asm("mov.u32 %0, %%cluster_ctarank;" : "=r"(rank));
    const float* X = xyz + (size_t)b * 3 * NPTS;
    const int base = rank * SLICE;

    for (int i = tid; i < SLICE; i += FPS_THREADS) {
        sx[i] = X[base + i];
        sy[i] = X[NPTS + base + i];
        sz[i] = X[2 * NPTS + base + i];
    }
    const uint32_t candBase = smem_u32(&cand[0][0]);
    const uint32_t resBase  = smem_u32(&res[0]);
    const uint32_t candBarA = smem_u32(&candBar);
    const uint32_t resBarA  = smem_u32(&resBar);
    if (tid == 0) {
        mbar_init(candBarA, FPS_CTAS);
        mbar_init(resBarA, 1);
    }
    __syncthreads();
    asm volatile("barrier.cluster.arrive.aligned;" ::: "memory");
    asm volatile("barrier.cluster.wait.aligned;" ::: "memory");

    float xr[PPT], yr[PPT], zr[PPT], dist[PPT];
    const int i0 = tid * PPT;
#pragma unroll
    for (int e = 0; e < PPT; e++) {
        xr[e] = sx[i0 + e]; yr[e] = sy[i0 + e]; zr[e] = sz[i0 + e];
        dist[e] = 1e10f;
    }
    float px = X[0], py = X[NPTS], pz = X[2 * NPTS];
    if (rank == 0 && tid == 0) {
        out[b * 3 * MCTR] = px;
        out[b * 3 * MCTR + MCTR] = py;
        out[b * 3 * MCTR + 2 * MCTR] = pz;
    }

    for (int step = 1; step < MCTR; step++) {
        const uint32_t parity = (uint32_t)((step - 1) & 1);
        float bv = -1.f; int bi = 0;
#pragma unroll
        for (int e = 0; e < PPT; e++) {
            float dx = fsub(xr[e], px), dy = fsub(yr[e], py), dz = fsub(zr[e], pz);
            float d  = fadd(fadd(fmul(dx, dx), fmul(dy, dy)), fmul(dz, dz));
            float nd = fminf(dist[e], d);
            dist[e] = nd;
            if (nd > bv) { bv = nd; bi = base + i0 + e; }
        }
#pragma unroll
        for (int off = 16; off > 0; off >>= 1) {
            float ov = __shfl_down_sync(0xffffffffu, bv, off);
            int   oi = __shfl_down_sync(0xffffffffu, bi, off);
            if (ov > bv || (ov == bv && oi < bi)) { bv = ov; bi = oi; }
        }
        if (lane == 0) { swv[w] = bv; swi[w] = bi; }
        __syncthreads();

        if (w == 0) {
            float v = (lane < 8) ? swv[lane] : -2.f;
            int   i = (lane < 8) ? swi[lane] : 0x7fffffff;
#pragma unroll
            for (int off = 4; off > 0; off >>= 1) {
                float ov = __shfl_xor_sync(0xffffffffu, v, off, 8);
                int   oi = __shfl_xor_sync(0xffffffffu, i, off, 8);
                if (ov > v || (ov == v && oi < i)) { v = ov; i = oi; }
            }
            if (lane == 0) {
                int li = i - base;
                float cx = sx[li], cy = sy[li], cz = sz[li];
                uint32_t ra = mapa_u32(candBase + rank * 32u, 0u);
                st_cluster_b32(ra,      __float_as_uint(v));
                st_cluster_b32(ra + 4,  (uint32_t)i);
                st_cluster_b32(ra + 8,  __float_as_uint(cx));
                st_cluster_b32(ra + 12, __float_as_uint(cy));
                st_cluster_b32(ra + 16, __float_as_uint(cz));
                mbar_arrive_remote(candBarA, 0u);
            }
            if (rank == 0) {
                mbar_wait_cluster(candBarA, parity);
                int rl = lane & 7;
                const float* sp = &cand[rl][0];
                float v2 = sp[0];
                int   i2 = __float_as_int(sp[1]);
                float x2 = sp[2], y2 = sp[3], z2 = sp[4];
#pragma unroll
                for (int off = 4; off > 0; off >>= 1) {
                    float ov = __shfl_xor_sync(0xffffffffu, v2, off, 8);
                    int   oi = __shfl_xor_sync(0xffffffffu, i2, off, 8);
                    float ox = __shfl_xor_sync(0xffffffffu, x2, off, 8);
                    float oy = __shfl_xor_sync(0xffffffffu, y2, off, 8);
                    float oz = __shfl_xor_sync(0xffffffffu, z2, off, 8);
                    if (ov > v2 || (ov == v2 && oi < i2)) { v2 = ov; i2 = oi; x2 = ox; y2 = oy; z2 = oz; }
                }
                if (lane < FPS_CTAS) {
                    uint32_t ra = mapa_u32(resBase, (uint32_t)lane);
                    st_cluster_b32(ra,     __float_as_uint(x2));
                    st_cluster_b32(ra + 4, __float_as_uint(y2));
                    st_cluster_b32(ra + 8, __float_as_uint(z2));
                    mbar_arrive_remote(resBarA, (uint32_t)lane);
                }
                if (lane == 0) {
                    out[b * 3 * MCTR + step] = x2;
                    out[b * 3 * MCTR + MCTR + step] = y2;
                    out[b * 3 * MCTR + 2 * MCTR + step] = z2;
                }
            }
        }
        mbar_wait_cluster(resBarA, parity);
        px = res[0]; py = res[1]; pz = res[2];
    }
}

// ============ W transpose precompute: [layer][k][o] fp32 ============
__global__ void __launch_bounds__(256) wsplit_kernel(const float* w0, const float* w1, const float* w2,
                                                     const float* w3, const float* w4, const float* w5)
{
    const float* Wp[6] = {w0, w1, w2, w3, w4, w5};
    int l = blockIdx.x;
    int Cin = c_cin[l], Cout = c_cout[l];
    const float* W = Wp[l];
    for (int t = threadIdx.x; t < 96 * 128; t += 256) {
        int k = t >> 7, o = t & 127;
        g_wT[l][k][o] = (o < Cout && k < Cin) ? W[o * Cin + k] : 0.f;
    }
}

// ============ Ball query (unchanged) ============
__global__ void __launch_bounds__(256) ballquery_kernel(const float* __restrict__ xyz,
                                                        const float* __restrict__ out,
                                                        int K, float r2)
{
    int warp = (blockIdx.x * blockDim.x + threadIdx.x) >> 5;
    int lane = threadIdx.x & 31;
    int b = warp >> 11, m = warp & (MCTR - 1);
    const float* nx = out + b * 3 * MCTR;
    float cx = nx[m], cy = nx[MCTR + m], cz = nx[2 * MCTR + m];
    float sqc = fadd(fadd(fmul(cx, cx), fmul(cy, cy)), fmul(cz, cz));
    const float* X = xyz + (size_t)b * 3 * NPTS;

    int cnt = 0, firstIdx = 0;
    bool haveFirst = false;
    int* dst = g_bq + (size_t)warp * K;
    for (int base = 0; base < NPTS; base += 32) {
        int n = base + lane;
        float x = X[n], y = X[NPTS + n], z = X[2 * NPTS + n];
        float sqx = fadd(fadd(fmul(x, x), fmul(y, y)), fmul(z, z));
        float dot = fadd(fadd(fmul(cx, x), fmul(cy, y)), fmul(cz, z));
        float d2 = fsub(fadd(sqc, sqx), fmul(2.0f, dot));
        bool pred = d2 < r2;
        unsigned msk = __ballot_sync(0xffffffffu, pred);
        if (!haveFirst && msk) { firstIdx = base + __ffs(msk) - 1; haveFirst = true; }
        if (pred) {
            int pos = cnt + __popc(msk & ((1u << lane) - 1u));
            if (pos < K) dst[pos] = n;
        }
        cnt += __popc(msk);
        if (cnt >= K) break;
    }
    if (cnt < K) {
        int fill = haveFirst ? firstIdx : 0;
        for (int p = cnt + lane; p < K; p += 32) dst[p] = fill;
    }
}

// ============ 3xTF32 tensor-core GEMM: fp32 smem, split at fragment load ============
// Dynamic smem = Kpad*132*8 bytes (X + W fp32) -> 2 CTAs/SM for all layers.
template <bool BN, bool GATHER>
__global__ void __launch_bounds__(256, 2) mma_gemm_kernel(const float* __restrict__ X,
                                                          float* __restrict__ Y,
                                                          int lidx,
                                                          int Cin, int Kpad, int Cout,
                                                          int ldc, int logK,
                                                          const float* __restrict__ xyz,
                                                          const float* __restrict__ feat,
                                                          const float* __restrict__ ctr)
{
    extern __shared__ __align__(16) float dsm[];
    float* Xs = dsm;                         // [Kpad][132]
    float* Ws = Xs + (size_t)Kpad * 132;     // [Kpad][132]
    __shared__ float  sa[128], sb2[128];
    __shared__ int    sidx[128];
    __shared__ float  sctr[3][128];
    __shared__ float2 sstat[2][128];

    const int tid = threadIdx.x;
    const int colBase = blockIdx.x * 128;

    if (BN && tid < Cin) { sa[tid] = g_a[tid]; sb2[tid] = g_bb[tid]; }
    if (GATHER && tid < 128) {
        int col = colBase + tid;
        sidx[tid] = g_bq[col];
        int mg = col >> logK;
        int bb_ = mg >> 11, m = mg & (MCTR - 1);
#pragma unroll
        for (int d = 0; d < 3; d++)
            sctr[d][tid] = ctr[bb_ * 3 * MCTR + d * MCTR + m];
    }
    __syncthreads();

    // ---- W staging: coalesced from pre-transposed [k][o] plane ----
    {
        const float* wt = &g_wT[lidx][0][0];
        for (int t = tid; t < Kpad * 128; t += 256) {
            int j = t & 127, k = t >> 7;
            Ws[k * 132 + j] = wt[t];
        }
    }
    // ---- X staging (fp32; gather/BN fused) ----
    {
        const float* Xp = nullptr;
        const float* Fp = nullptr;
        if (GATHER) {
            int bb_ = colBase >> (logK + 11);
            Xp = xyz + (size_t)bb_ * 3 * NPTS;
            Fp = feat + (size_t)bb_ * 64 * NPTS;
        }
        for (int t = tid; t < Kpad * 128; t += 256) {
            int j = t & 127, k = t >> 7;
            float v = 0.f;
            if (k < Cin) {
                if (GATHER) {
                    int n = sidx[j];
                    if (k < 3) v = Xp[k * NPTS + n] - sctr[k][j];
                    else       v = Fp[(k - 3) * NPTS + n];
                } else {
                    v = X[(size_t)k * ldc + colBase + j];
                    if (BN) v = fmaxf(0.f, fmaf(sa[k], v, sb2[k]));
                }
            }
            Xs[k * 132 + j] = v;
        }
    }
    __syncthreads();

    const int w = tid >> 5, lane = tid & 31;
    const int g = lane >> 2, tg = lane & 3;
    const int mBase = (w & 3) * 32, nBase = (w >> 2) * 64;

    float acc[2][8][4];
#pragma unroll
    for (int mt = 0; mt < 2; mt++)
#pragma unroll
        for (int nt = 0; nt < 8; nt++)
#pragma unroll
            for (int c = 0; c < 4; c++) acc[mt][nt][c] = 0.f;

    for (int k0 = 0; k0 < Kpad; k0 += 8) {
        uint32_t ah[2][4], al[2][4];
        const int kr0 = (k0 + tg) * 132, kr1 = (k0 + tg + 4) * 132;
#pragma unroll
        for (int mt = 0; mt < 2; mt++) {
            int r = mBase + mt * 16 + g;
            split_tf32(Ws[kr0 + r],     ah[mt][0], al[mt][0]);
            split_tf32(Ws[kr0 + r + 8], ah[mt][1], al[mt][1]);
            split_tf32(Ws[kr1 + r],     ah[mt][2], al[mt][2]);
            split_tf32(Ws[kr1 + r + 8], ah[mt][3], al[mt][3]);
        }
#pragma unroll
        for (int nt = 0; nt < 8; nt++) {
            int c = nBase + nt * 8 + g;
            uint32_t bh0, bl0, bh1, bl1;
            split_tf32(Xs[kr0 + c], bh0, bl0);
            split_tf32(Xs[kr1 + c], bh1, bl1);
#pragma unroll
            for (int mt = 0; mt < 2; mt++) {
                MMA_TF32(acc[mt][nt], ah[mt], bl0, bl1);
                MMA_TF32(acc[mt][nt], al[mt], bh0, bh1);
                MMA_TF32(acc[mt][nt], ah[mt], bh0, bh1);
            }
        }
    }
    __syncthreads();   // planes free; reuse as D staging

    // ---- stats from register fragments (deterministic) ----
    {
        float s[4] = {0.f, 0.f, 0.f, 0.f}, q[4] = {0.f, 0.f, 0.f, 0.f};
#pragma unroll
        for (int mt = 0; mt < 2; mt++)
#pragma unroll
            for (int nt = 0; nt < 8; nt++) {
                float v0 = acc[mt][nt][0], v1 = acc[mt][nt][1];
                float v2 = acc[mt][nt][2], v3 = acc[mt][nt][3];
                s[mt * 2 + 0] += v0 + v1; q[mt * 2 + 0] += v0 * v0 + v1 * v1;
                s[mt * 2 + 1] += v2 + v3; q[mt * 2 + 1] += v2 * v2 + v3 * v3;
            }
#pragma unroll
        for (int off = 1; off <= 2; off <<= 1)
#pragma unroll
            for (int i = 0; i < 4; i++) {
                s[i] += __shfl_xor_sync(0xffffffffu, s[i], off);
                q[i] += __shfl_xor_sync(0xffffffffu, q[i], off);
            }
        if (tg == 0) {
            int nw = w >> 2;
            sstat[nw][mBase + g]      = make_float2(s[0], q[0]);
            sstat[nw][mBase + 8 + g]  = make_float2(s[1], q[1]);
            sstat[nw][mBase + 16 + g] = make_float2(s[2], q[2]);
            sstat[nw][mBase + 24 + g] = make_float2(s[3], q[3]);
        }
    }

    // ---- D -> smem staging [row][132] ----
    {
        float* Ds = dsm;
#pragma unroll
        for (int mt = 0; mt < 2; mt++) {
            int r = mBase + mt * 16 + g;
#pragma unroll
            for (int nt = 0; nt < 8; nt++) {
                int c = nBase + nt * 8 + 2 * tg;
                *(float2*)&Ds[r * 132 + c]       = make_float2(acc[mt][nt][0], acc[mt][nt][1]);
                *(float2*)&Ds[(r + 8) * 132 + c] = make_float2(acc[mt][nt][2], acc[mt][nt][3]);
            }
        }
    }
    __syncthreads();

    if (tid < 128) {
        float2 a0 = sstat[0][tid], b0 = sstat[1][tid];
        g_part[(size_t)blockIdx.x * 128 + tid] = make_float2(a0.x + b0.x, a0.y + b0.y);
    }
    {
        const float* Ds = dsm;
        for (int idx = tid; idx < Cout * 32; idx += 256) {
            int o = idx >> 5, jj = idx & 31;
            float4 v = *(const float4*)&Ds[o * 132 + jj * 4];
            *(float4*)&Y[(size_t)o * ldc + colBase + jj * 4] = v;
        }
    }
}

// ============ deterministic stats reduce -> BN scale/shift (unchanged) ============
__global__ void __launch_bounds__(256) reduce_stats_kernel(const float* __restrict__ gam,
                                                           const float* __restrict__ bet,
                                                           int R, float inv_n)
{
    __shared__ float ss[256], sq[256];
    int c = blockIdx.x, tid = threadIdx.x;
    float s = 0.f, q = 0.f;
    for (int r = tid; r < R; r += 256) {
        float2 v = g_part[(size_t)r * 128 + c];
        s += v.x; q += v.y;
    }
    ss[tid] = s; sq[tid] = q;
    __syncthreads();
    for (int off = 128; off > 0; off >>= 1) {
        if (tid < off) { ss[tid] += ss[tid + off]; sq[tid] += sq[tid + off]; }
        __syncthreads();
    }
    if (tid == 0) {
        float mu = ss[0] * inv_n;
        float var = sq[0] * inv_n - mu * mu;
        if (var < 0.f) var = 0.f;
        float a = gam[c] * rsqrtf(var + 1e-5f);
        g_a[c] = a;
        g_bb[c] = bet[c] - mu * a;
    }
}

// ============ BN + ReLU + max over K -> output features (unchanged) ============
__global__ void __launch_bounds__(1024) maxpool_kernel(const float* __restrict__ Y,
                                                       float* __restrict__ out,
                                                       int K, int chanOff, int ldc)
{
    int gw = (blockIdx.x * 1024 + threadIdx.x) >> 5;
    int lane = threadIdx.x & 31;
    int o = gw & 127;
    int mg = gw >> 7;
    int b = mg >> 11, m = mg & (MCTR - 1);
    float a = g_a[o], bb = g_bb[o];
    const float* src = Y + (size_t)o * ldc + (size_t)mg * K;
    float v = 0.f;
    for (int k = lane; k < K; k += 32)
        v = fmaxf(v, fmaf(a, src[k], bb));
#pragma unroll
    for (int off = 16; off > 0; off >>= 1)
        v = fmaxf(v, __shfl_xor_sync(0xffffffffu, v, off));
    if (lane == 0)
        out[24576 + ((size_t)(b * 256 + chanOff + o)) * MCTR + m] = v;
}

// ==================== host side ====================
extern "C" void kernel_launch(void* const* d_in, const int* in_sizes, int n_in,
                              void* d_out, int out_size)
{
    const float* xyz  = (const float*)d_in[0];
    const float* feat = (const float*)d_in[1];
    float* out = (float*)d_out;

    fps_cluster_kernel<<<4 * FPS_CTAS, FPS_THREADS>>>(xyz, out);

    wsplit_kernel<<<6, 256>>>((const float*)d_in[2],  (const float*)d_in[5],  (const float*)d_in[8],
                              (const float*)d_in[11], (const float*)d_in[14], (const float*)d_in[17]);

    const int MAX_DSM = 96 * 132 * 8;   // 101376 bytes
    cudaFuncSetAttribute(mma_gemm_kernel<false, true>,
                         cudaFuncAttributeMaxDynamicSharedMemorySize, MAX_DSM);
    cudaFuncSetAttribute(mma_gemm_kernel<true, false>,
                         cudaFuncAttributeMaxDynamicSharedMemorySize, MAX_DSM);

    const int KS[2] = {32, 64};
    const float R2[2] = {(float)(0.2 * 0.2), (float)(0.4 * 0.4)};
    const int CH[2][3] = {{64, 64, 128}, {64, 96, 128}};
    const int KPAD[2][3] = {{72, 64, 64}, {72, 64, 96}};

    for (int s = 0; s < 2; s++) {
        int K = KS[s];
        int logK = (K == 32) ? 5 : 6;
        int cols = 4 * MCTR * K;
        int nBlk = cols / 128;
        float inv_n = 1.0f / (float)cols;

        ballquery_kernel<<<1024, 256>>>(xyz, out, K, R2[s]);

        const float *Gl[3], *Bl[3];
        for (int l = 0; l < 3; l++) {
            Gl[l] = (const float*)d_in[2 + s * 9 + l * 3 + 1];
            Bl[l] = (const float*)d_in[2 + s * 9 + l * 3 + 2];
        }
        float *pA, *pB;
        cudaGetSymbolAddress((void**)&pA, g_bufA);
        cudaGetSymbolAddress((void**)&pB, g_bufB);

        int c0 = CH[s][0], c1 = CH[s][1], c2 = CH[s][2];

        // L0: gather fused -> B(c0)
        mma_gemm_kernel<false, true><<<nBlk, 256, KPAD[s][0] * 132 * 8>>>(
            nullptr, pB, s * 3 + 0, 67, KPAD[s][0], c0, cols, logK, xyz, feat, out);
        reduce_stats_kernel<<<c0, 256>>>(Gl[0], Bl[0], nBlk, inv_n);

        // L1: B (bn+relu fused) -> A(c1)
        mma_gemm_kernel<true, false><<<nBlk, 256, KPAD[s][1] * 132 * 8>>>(
            pB, pA, s * 3 + 1, c0, KPAD[s][1], c1, cols, logK, xyz, feat, out);
        reduce_stats_kernel<<<c1, 256>>>(Gl[1], Bl[1], nBlk, inv_n);

        // L2: A (bn+relu fused) -> B(128)
        mma_gemm_kernel<true, false><<<nBlk, 256, KPAD[s][2] * 132 * 8>>>(
            pA, pB, s * 3 + 2, c1, KPAD[s][2], c2, cols, logK, xyz, feat, out);
        reduce_stats_kernel<<<c2, 256>>>(Gl[2], Bl[2], nBlk, inv_n);

        maxpool_kernel<<<(4 * MCTR * 128) / 32, 1024>>>(pB, out, K, s * 128, cols);
    }
}